// round 3
// baseline (speedup 1.0000x reference)
#include <cuda_runtime.h>
#include <cuda_bf16.h>

// ChamferLoss: pred[32768,3], target[32768,3] (float32)
// out = mean_i min_j |p_i - t_j|^2 + mean_j min_i |t_j - p_i|^2
//
// Strategy:
//  |x-y|^2 = |x|^2 + (|y|^2 - 2 x.y); fold |x|^2 out of the min.
//  Pack targets 2-at-a-time and use Blackwell f32x2 packed mul/fma:
//  2 packed fma-pipe ops per (query,target) pair. Register-tile Q=4
//  queries per thread so shared loads amortize.

#define N_PTS      32768
#define N_PAIRS    16384          // N_PTS/2
#define THREADS    128
#define QPT        4              // queries per thread
#define QBS        (THREADS*QPT)  // 512 queries per block
#define QBLOCKS    (N_PTS/QBS)    // 64
#define SEGS       8
#define PAIRS_PER_SEG (N_PAIRS/SEGS)  // 2048 pairs = 4096 points
#define TILE_PAIRS 1024
#define NEG2PACK   0xC0000000C0000000ULL  // (-2.0f, -2.0f)
#define INF_BITS   0x7F800000u

// Scratch (static __device__, allocation-free).
// g_packA[set][p] = (y0_a, y0_b, y1_a, y1_b) of points 2p, 2p+1
// g_packB[set][p] = (y2_a, y2_b, |y_a|^2, |y_b|^2)
__device__ ulonglong2 g_packA[2][N_PAIRS];
__device__ ulonglong2 g_packB[2][N_PAIRS];
__device__ unsigned   g_min[2 * N_PTS];

// ---------------- packed f32x2 helpers ----------------
__device__ __forceinline__ unsigned long long mul2(unsigned long long a,
                                                   unsigned long long b) {
    unsigned long long d;
    asm("mul.rn.f32x2 %0, %1, %2;" : "=l"(d) : "l"(a), "l"(b));
    return d;
}
__device__ __forceinline__ unsigned long long fma2(unsigned long long a,
                                                   unsigned long long b,
                                                   unsigned long long c) {
    unsigned long long d;
    asm("fma.rn.f32x2 %0, %1, %2, %3;" : "=l"(d) : "l"(a), "l"(b), "l"(c));
    return d;
}
__device__ __forceinline__ void unpack2(unsigned long long d, float& lo, float& hi) {
    asm("mov.b64 {%0, %1}, %2;" : "=f"(lo), "=f"(hi) : "l"(d));
}
__device__ __forceinline__ unsigned long long pack2(float lo, float hi) {
    unsigned long long d;
    asm("mov.b64 %0, {%1, %2};" : "=l"(d) : "f"(lo), "f"(hi));
    return d;
}

// ---------------- init: mins to +inf ----------------
__global__ void chamfer_init_kernel() {
    int i = blockIdx.x * blockDim.x + threadIdx.x;
    if (i < 2 * N_PTS) g_min[i] = INF_BITS;
}

// ---------------- prep: build packed SoA + norms ----------------
__global__ void chamfer_prep_kernel(const float* __restrict__ pred,
                                    const float* __restrict__ target) {
    int tid = blockIdx.x * blockDim.x + threadIdx.x;   // 0 .. 2*N_PAIRS-1
    if (tid >= 2 * N_PAIRS) return;
    int set = tid >> 14;          // /N_PAIRS
    int p   = tid & (N_PAIRS - 1);
    const float* src = (set == 0) ? pred : target;
    int ia = 6 * p;               // point 2p
    float a0 = src[ia + 0], a1 = src[ia + 1], a2 = src[ia + 2];
    float b0 = src[ia + 3], b1 = src[ia + 4], b2 = src[ia + 5];
    float na = a0 * a0 + a1 * a1 + a2 * a2;
    float nb = b0 * b0 + b1 * b1 + b2 * b2;
    ulonglong2 A, B;
    A.x = pack2(a0, b0);
    A.y = pack2(a1, b1);
    B.x = pack2(a2, b2);
    B.y = pack2(na, nb);
    g_packA[set][p] = A;
    g_packB[set][p] = B;
}

// ---------------- main: per-query min over a target segment ----------------
__global__ void __launch_bounds__(THREADS)
chamfer_main_kernel(const float* __restrict__ pred,
                    const float* __restrict__ target) {
    __shared__ ulonglong2 sA[TILE_PAIRS];
    __shared__ ulonglong2 sB[TILE_PAIRS];

    const int dir = blockIdx.z;                 // 0: pred->target, 1: target->pred
    const int seg = blockIdx.y;
    const int t   = threadIdx.x;
    const float* qsrc = (dir == 0) ? pred : target;
    const int tset = (dir == 0) ? 1 : 0;        // other set is the target set
    const ulonglong2* __restrict__ tA = g_packA[tset];
    const ulonglong2* __restrict__ tB = g_packB[tset];

    // Register-tiled queries: broadcast packs (x,x)
    int qi[QPT];
    unsigned long long p0[QPT], p1[QPT], p2[QPT];
    float nx[QPT], mlo[QPT], mhi[QPT];
#pragma unroll
    for (int q = 0; q < QPT; q++) {
        qi[q] = blockIdx.x * QBS + t + q * THREADS;
        float x0 = qsrc[3 * qi[q] + 0];
        float x1 = qsrc[3 * qi[q] + 1];
        float x2 = qsrc[3 * qi[q] + 2];
        nx[q] = x0 * x0 + x1 * x1 + x2 * x2;
        p0[q] = pack2(x0, x0);
        p1[q] = pack2(x1, x1);
        p2[q] = pack2(x2, x2);
        mlo[q] = __int_as_float(0x7F800000);
        mhi[q] = __int_as_float(0x7F800000);
    }

    const int segBase = seg * PAIRS_PER_SEG;
#pragma unroll 1
    for (int tile = 0; tile < PAIRS_PER_SEG / TILE_PAIRS; tile++) {
        int base = segBase + tile * TILE_PAIRS;
        // cooperative tile load (LDG.128 -> STS.128)
#pragma unroll
        for (int k = 0; k < TILE_PAIRS / THREADS; k++) {
            int idx = t + k * THREADS;
            sA[idx] = tA[base + idx];
            sB[idx] = tB[base + idx];
        }
        __syncthreads();

#pragma unroll 4
        for (int j = 0; j < TILE_PAIRS; j++) {
            ulonglong2 a = sA[j];   // (y0 pair, y1 pair)
            ulonglong2 b = sB[j];   // (y2 pair, ny pair)
#pragma unroll
            for (int q = 0; q < QPT; q++) {
                unsigned long long acc = mul2(a.x, p0[q]);
                acc = fma2(a.y, p1[q], acc);
                acc = fma2(b.x, p2[q], acc);
                // d = ny - 2*dot
                unsigned long long d = fma2(acc, NEG2PACK, b.y);
                float lo, hi;
                unpack2(d, lo, hi);
                mlo[q] = fminf(mlo[q], lo);
                mhi[q] = fminf(mhi[q], hi);
            }
        }
        __syncthreads();
    }

#pragma unroll
    for (int q = 0; q < QPT; q++) {
        float m = fminf(mlo[q], mhi[q]) + nx[q];
        m = fmaxf(m, 0.0f);   // squared distance; guards bit-order for atomicMin
        atomicMin(&g_min[dir * N_PTS + qi[q]], __float_as_uint(m));
    }
}

// ---------------- final deterministic reduction ----------------
__global__ void chamfer_reduce_kernel(float* __restrict__ out) {
    __shared__ float s[512];
    int t = threadIdx.x;
    float acc = 0.0f;
    for (int i = t; i < 2 * N_PTS; i += 512)
        acc += __uint_as_float(g_min[i]);
    s[t] = acc;
    __syncthreads();
    for (int stride = 256; stride > 0; stride >>= 1) {
        if (t < stride) s[t] += s[t + stride];
        __syncthreads();
    }
    if (t == 0) out[0] = s[0] / (float)N_PTS;
}

extern "C" void kernel_launch(void* const* d_in, const int* in_sizes, int n_in,
                              void* d_out, int out_size) {
    const float* pred   = (const float*)d_in[0];
    const float* target = (const float*)d_in[1];
    float* out = (float*)d_out;

    chamfer_init_kernel<<<(2 * N_PTS + 1023) / 1024, 1024>>>();
    chamfer_prep_kernel<<<(2 * N_PAIRS + 255) / 256, 256>>>(pred, target);
    dim3 grid(QBLOCKS, SEGS, 2);
    chamfer_main_kernel<<<grid, THREADS>>>(pred, target);
    chamfer_reduce_kernel<<<1, 512>>>(out);
}

// round 5
// speedup vs baseline: 1.1412x; 1.1412x over previous
#include <cuda_runtime.h>
#include <cuda_bf16.h>

// ChamferLoss: pred[32768,3], target[32768,3] (float32)
// out = mean_i min_j |p_i - t_j|^2 + mean_j min_i |t_j - p_i|^2
//
// |x-y|^2 = |x|^2 + (|y|^2 - 2 x.y); fold |x|^2 out of the min.
// Prep stores targets pre-scaled by -2 plus their norm, packed 2-wide, so the
// inner loop is exactly 3 packed f32x2 FMAs per 2 targets (fma-pipe bound).

#define N_PTS      32768
#define N_PAIRS    16384          // N_PTS/2
#define THREADS    128
#define QPT        4              // queries per thread
#define QBS        (THREADS*QPT)  // 512 queries per block
#define QBLOCKS    (N_PTS/QBS)    // 64
#define SEGS       8
#define PAIRS_PER_SEG (N_PAIRS/SEGS)  // 2048 pairs = 4096 points
#define TILE_PAIRS 1024
#define INF_BITS   0x7F800000u
#define RED1_BLOCKS 64
#define RED1_SPAN   (2*N_PTS/RED1_BLOCKS)  // 1024 values per block

// Scratch (static __device__, allocation-free).
// g_packA[set][p] = (-2*y0_a, -2*y0_b, -2*y1_a, -2*y1_b) of points 2p, 2p+1
// g_packB[set][p] = (-2*y2_a, -2*y2_b, |y_a|^2, |y_b|^2)
__device__ ulonglong2 g_packA[2][N_PAIRS];
__device__ ulonglong2 g_packB[2][N_PAIRS];
__device__ unsigned   g_min[2 * N_PTS];
__device__ float      g_part[RED1_BLOCKS];

// ---------------- packed f32x2 helpers ----------------
__device__ __forceinline__ unsigned long long fma2(unsigned long long a,
                                                   unsigned long long b,
                                                   unsigned long long c) {
    unsigned long long d;
    asm("fma.rn.f32x2 %0, %1, %2, %3;" : "=l"(d) : "l"(a), "l"(b), "l"(c));
    return d;
}
__device__ __forceinline__ void unpack2(unsigned long long d, float& lo, float& hi) {
    asm("mov.b64 {%0, %1}, %2;" : "=f"(lo), "=f"(hi) : "l"(d));
}
__device__ __forceinline__ unsigned long long pack2(float lo, float hi) {
    unsigned long long d;
    asm("mov.b64 %0, {%1, %2};" : "=l"(d) : "f"(lo), "f"(hi));
    return d;
}

// ---------------- prep: init mins + build packed SoA (-2y, |y|^2) ----------
__global__ void chamfer_prep_kernel(const float* __restrict__ pred,
                                    const float* __restrict__ target) {
    int tid = blockIdx.x * blockDim.x + threadIdx.x;   // 0 .. 2*N_PTS-1
    if (tid < 2 * N_PTS) g_min[tid] = INF_BITS;
    if (tid >= 2 * N_PAIRS) return;
    int set = tid >> 14;          // /N_PAIRS
    int p   = tid & (N_PAIRS - 1);
    const float* src = (set == 0) ? pred : target;
    int ia = 6 * p;               // point 2p
    float a0 = src[ia + 0], a1 = src[ia + 1], a2 = src[ia + 2];
    float b0 = src[ia + 3], b1 = src[ia + 4], b2 = src[ia + 5];
    float na = a0 * a0 + a1 * a1 + a2 * a2;
    float nb = b0 * b0 + b1 * b1 + b2 * b2;
    ulonglong2 A, B;
    A.x = pack2(-2.0f * a0, -2.0f * b0);
    A.y = pack2(-2.0f * a1, -2.0f * b1);
    B.x = pack2(-2.0f * a2, -2.0f * b2);
    B.y = pack2(na, nb);
    g_packA[set][p] = A;
    g_packB[set][p] = B;
}

// ---------------- main: per-query min over a target segment ----------------
__global__ void __launch_bounds__(THREADS)
chamfer_main_kernel(const float* __restrict__ pred,
                    const float* __restrict__ target) {
    __shared__ ulonglong2 sA[TILE_PAIRS];
    __shared__ ulonglong2 sB[TILE_PAIRS];

    const int dir = blockIdx.z;                 // 0: pred->target, 1: target->pred
    const int seg = blockIdx.y;
    const int t   = threadIdx.x;
    const float* qsrc = (dir == 0) ? pred : target;
    const int tset = (dir == 0) ? 1 : 0;        // other set is the target set
    const ulonglong2* __restrict__ tA = g_packA[tset];
    const ulonglong2* __restrict__ tB = g_packB[tset];

    // Register-tiled queries: broadcast packs (x,x)
    int qi[QPT];
    unsigned long long p0[QPT], p1[QPT], p2[QPT];
    float nx[QPT], mlo[QPT], mhi[QPT];
#pragma unroll
    for (int q = 0; q < QPT; q++) {
        qi[q] = blockIdx.x * QBS + t + q * THREADS;
        float x0 = qsrc[3 * qi[q] + 0];
        float x1 = qsrc[3 * qi[q] + 1];
        float x2 = qsrc[3 * qi[q] + 2];
        nx[q] = x0 * x0 + x1 * x1 + x2 * x2;
        p0[q] = pack2(x0, x0);
        p1[q] = pack2(x1, x1);
        p2[q] = pack2(x2, x2);
        mlo[q] = __int_as_float(0x7F800000);
        mhi[q] = __int_as_float(0x7F800000);
    }

    const int segBase = seg * PAIRS_PER_SEG;
#pragma unroll 1
    for (int tile = 0; tile < PAIRS_PER_SEG / TILE_PAIRS; tile++) {
        int base = segBase + tile * TILE_PAIRS;
        // cooperative tile load (LDG.128 -> STS.128)
#pragma unroll
        for (int k = 0; k < TILE_PAIRS / THREADS; k++) {
            int idx = t + k * THREADS;
            sA[idx] = tA[base + idx];
            sB[idx] = tB[base + idx];
        }
        __syncthreads();

#pragma unroll 4
        for (int j = 0; j < TILE_PAIRS; j++) {
            ulonglong2 a = sA[j];   // (-2*y0 pair, -2*y1 pair)
            ulonglong2 b = sB[j];   // (-2*y2 pair, ny pair)
#pragma unroll
            for (int q = 0; q < QPT; q++) {
                // d = ny - 2*(x0*y0 + x1*y1 + x2*y2), packed for 2 targets
                unsigned long long d =
                    fma2(a.x, p0[q], fma2(a.y, p1[q], fma2(b.x, p2[q], b.y)));
                float lo, hi;
                unpack2(d, lo, hi);
                mlo[q] = fminf(mlo[q], lo);
                mhi[q] = fminf(mhi[q], hi);
            }
        }
        __syncthreads();
    }

#pragma unroll
    for (int q = 0; q < QPT; q++) {
        float m = fminf(mlo[q], mhi[q]) + nx[q];
        m = fmaxf(m, 0.0f);   // squared distance; guards bit-order for atomicMin
        atomicMin(&g_min[dir * N_PTS + qi[q]], __float_as_uint(m));
    }
}

// ---------------- deterministic 2-stage reduction ----------------
__global__ void __launch_bounds__(256)
chamfer_reduce1_kernel() {
    __shared__ float s[256];
    int t = threadIdx.x;
    int base = blockIdx.x * RED1_SPAN;
    float acc = 0.0f;
#pragma unroll
    for (int k = 0; k < RED1_SPAN / 256; k++)
        acc += __uint_as_float(g_min[base + t + k * 256]);
    s[t] = acc;
    __syncthreads();
    for (int stride = 128; stride > 0; stride >>= 1) {
        if (t < stride) s[t] += s[t + stride];
        __syncthreads();
    }
    if (t == 0) g_part[blockIdx.x] = s[0];
}

__global__ void __launch_bounds__(64)
chamfer_reduce2_kernel(float* __restrict__ out) {
    __shared__ float s[64];
    int t = threadIdx.x;
    s[t] = g_part[t];
    __syncthreads();
    for (int stride = 32; stride > 0; stride >>= 1) {
        if (t < stride) s[t] += s[t + stride];
        __syncthreads();
    }
    if (t == 0) out[0] = s[0] / (float)N_PTS;
}

extern "C" void kernel_launch(void* const* d_in, const int* in_sizes, int n_in,
                              void* d_out, int out_size) {
    const float* pred   = (const float*)d_in[0];
    const float* target = (const float*)d_in[1];
    float* out = (float*)d_out;

    chamfer_prep_kernel<<<(2 * N_PTS + 255) / 256, 256>>>(pred, target);
    dim3 grid(QBLOCKS, SEGS, 2);
    chamfer_main_kernel<<<grid, THREADS>>>(pred, target);
    chamfer_reduce1_kernel<<<RED1_BLOCKS, 256>>>();
    chamfer_reduce2_kernel<<<1, 64>>>(out);
}